// round 9
// baseline (speedup 1.0000x reference)
#include <cuda_runtime.h>
#include <math.h>

#define NN      100000   // nodes
#define HID     64
#define NL      40
#define NNZ_MAX 2500000  // feature nonzeros
#define NE_MAX  1700000  // edges incl self loops
#define SCAN_N  (2 * NN)

// ---------------- scratch (no allocations allowed) ----------------
__device__ __align__(256) float g_h [NN * HID];   // layer-1 activations
__device__ __align__(256) float g_z [NN * NL];    // dense-layer output

__device__ int  g_cnt[SCAN_N];      // per-row counts (f rows | e rows)
__device__ int  g_off[SCAN_N];      // per-row segment begin
__device__ int  g_cur[SCAN_N];      // fill cursor; after fill == segment end
__device__ int  g_counter[2];       // unordered base allocators (f, e)
__device__ __align__(16) int2 g_fcv[NNZ_MAX];  // (col, val-bits) feature rowsegs
__device__ __align__(16) int2 g_ecv[NE_MAX];   // (col, weight-bits) edge rowsegs

// ---------------- CSR build ----------------

__global__ void k_zero() {
    int i = blockIdx.x * blockDim.x + threadIdx.x;
    if (i < SCAN_N) g_cnt[i] = 0;
    if (i < 2) g_counter[i] = 0;
}

__global__ void k_count(const int* __restrict__ frow, const int* __restrict__ erow,
                        int nnz, int ne) {
    int i = blockIdx.x * blockDim.x + threadIdx.x;
    if (i < nnz)            atomicAdd(&g_cnt[frow[i]], 1);
    else if (i < nnz + ne)  atomicAdd(&g_cnt[NN + erow[i - nnz]], 1);
}

// Per-block scan + one atomic base per block. Row ordering in the value
// arrays is arbitrary; only disjoint contiguous per-row segments matter.
__global__ void k_offsets() {
    __shared__ int s[2][1024];
    __shared__ int sbase;
    int tid = threadIdx.x;
    int sec = blockIdx.y;                 // 0 = features, 1 = edges
    int gid = blockIdx.x * 1024 + tid;
    int idx = sec * NN + gid;
    int v = (gid < NN) ? g_cnt[idx] : 0;
    int buf = 0;
    s[0][tid] = v; __syncthreads();
#pragma unroll
    for (int o = 1; o < 1024; o <<= 1) {
        int nb = buf ^ 1;
        s[nb][tid] = s[buf][tid] + (tid >= o ? s[buf][tid - o] : 0);
        buf = nb; __syncthreads();
    }
    int incl = s[buf][tid];
    if (tid == 1023) sbase = atomicAdd(&g_counter[sec], incl);
    __syncthreads();
    if (gid < NN) {
        int o = sbase + incl - v;
        g_off[idx] = o;
        g_cur[idx] = o;
    }
}

__global__ void k_fill(const int* __restrict__ frow, const int* __restrict__ fcol,
                       const float* __restrict__ fval,
                       const int* __restrict__ erow, const int* __restrict__ ecol,
                       const float* __restrict__ ew, int nnz, int ne) {
    int i = blockIdx.x * blockDim.x + threadIdx.x;
    if (i < nnz) {
        int r = frow[i];
        int pos = atomicAdd(&g_cur[r], 1);
        g_fcv[pos] = make_int2(fcol[i], __float_as_int(fval[i]));
    } else if (i < nnz + ne) {
        int k = i - nnz;
        int r = erow[k];
        int pos = atomicAdd(&g_cur[NN + r], 1);
        g_ecv[pos] = make_int2(ecol[k], __float_as_int(ew[k]));
    }
}

// ---------------- forward pass ----------------

// h[row] = b1 + sum_p val_p * W1[col_p]   (warp per row, float2 per lane)
__global__ void __launch_bounds__(256) k_feat_gather(const float* __restrict__ W1,
                                                     const float* __restrict__ b1) {
    int gid = blockIdx.x * blockDim.x + threadIdx.x;
    int row = gid >> 5;
    int lane = threadIdx.x & 31;
    if (row >= NN) return;
    int beg = g_off[row], end = g_cur[row];
    float2 acc = reinterpret_cast<const float2*>(b1)[lane];
#pragma unroll 2
    for (int p = beg; p < end; p++) {
        int2 cv = g_fcv[p];
        float v = __int_as_float(cv.y);
        float2 w = *reinterpret_cast<const float2*>(W1 + (size_t)cv.x * HID + 2 * lane);
        acc.x += v * w.x;
        acc.y += v * w.y;
    }
    *reinterpret_cast<float2*>(g_h + (size_t)row * HID + 2 * lane) = acc;
}

// z[row] = relu(sum_e w_e * h[col_e]) @ W2 + b2   (warp per row; W2^T in smem)
__global__ void __launch_bounds__(256) k_prop_dense(const float* __restrict__ W2,
                                                    const float* __restrict__ b2) {
    __shared__ float sW[NL * 65];     // transposed, padded: sW[j*65 + t]
    __shared__ float sh[8][HID];
    __shared__ float sb[NL];
    int tid = threadIdx.x;
    for (int i = tid; i < HID * NL; i += 256) {
        int t = i / NL, j = i % NL;
        sW[j * 65 + t] = W2[i];
    }
    if (tid < NL) sb[tid] = b2[tid];
    __syncthreads();

    int warp = tid >> 5, lane = tid & 31;
    int row = blockIdx.x * 8 + warp;       // grid = 12500, exact
    int beg = g_off[NN + row], end = g_cur[NN + row];

    float2 acc = make_float2(0.f, 0.f);
#pragma unroll 2
    for (int p = beg; p < end; p++) {
        int2 cv = g_ecv[p];
        float w = __int_as_float(cv.y);
        float2 h = *reinterpret_cast<const float2*>(g_h + (size_t)cv.x * HID + 2 * lane);
        acc.x += w * h.x;
        acc.y += w * h.y;
    }
    sh[warp][2 * lane]     = fmaxf(acc.x, 0.f);
    sh[warp][2 * lane + 1] = fmaxf(acc.y, 0.f);
    __syncwarp();

    float a0 = sb[lane];
    float a1 = (lane < NL - 32) ? sb[32 + lane] : 0.f;
#pragma unroll
    for (int t = 0; t < HID; t++) {
        float hv = sh[warp][t];
        a0 += hv * sW[lane * 65 + t];
        if (lane < NL - 32) a1 += hv * sW[(32 + lane) * 65 + t];
    }
    float* zrow = g_z + (size_t)row * NL;
    zrow[lane] = a0;
    if (lane < NL - 32) zrow[32 + lane] = a1;
}

// out[row] = log_softmax(sum_e w_e * z[col_e])   (warp per row, fused)
__global__ void __launch_bounds__(256) k_zq(float* __restrict__ out) {
    int tid = threadIdx.x;
    int warp = tid >> 5, lane = tid & 31;
    int row = blockIdx.x * 8 + warp;       // grid = 12500, exact
    int beg = g_off[NN + row], end = g_cur[NN + row];

    float a0 = 0.f, a1 = 0.f;
#pragma unroll 2
    for (int p = beg; p < end; p++) {
        int2 cv = g_ecv[p];
        float w = __int_as_float(cv.y);
        const float* zr = g_z + (size_t)cv.x * NL;
        a0 += w * zr[lane];
        if (lane < NL - 32) a1 += w * zr[32 + lane];
    }

    float v1 = (lane < NL - 32) ? a1 : -1e30f;
    float m = fmaxf(a0, v1);
#pragma unroll
    for (int o = 16; o > 0; o >>= 1) m = fmaxf(m, __shfl_xor_sync(0xffffffffu, m, o));
    float s = __expf(a0 - m) + ((lane < NL - 32) ? __expf(a1 - m) : 0.f);
#pragma unroll
    for (int o = 16; o > 0; o >>= 1) s += __shfl_xor_sync(0xffffffffu, s, o);
    float l = m + logf(s);

    float* orow = out + (size_t)row * NL;
    orow[lane] = a0 - l;
    if (lane < NL - 32) orow[32 + lane] = a1 - l;
}

// ---------------- launch ----------------
extern "C" void kernel_launch(void* const* d_in, const int* in_sizes, int n_in,
                              void* d_out, int out_size) {
    const int*   fidx = (const int*)  d_in[0];   // int32
    const float* fval = (const float*)d_in[1];
    const int*   eidx = (const int*)  d_in[2];   // int32
    const float* ew   = (const float*)d_in[3];
    const float* W1   = (const float*)d_in[4];
    const float* b1   = (const float*)d_in[5];
    const float* W2   = (const float*)d_in[6];
    const float* b2   = (const float*)d_in[7];
    float* out = (float*)d_out;

    int nnz = in_sizes[0] / 2;   // feature_indices is [2, NNZ]
    int ne  = in_sizes[2] / 2;   // edge_indices is [2, E]

    const int* frow = fidx;
    const int* fcol = fidx + nnz;
    const int* erow = eidx;
    const int* ecol = eidx + ne;
    int tot = nnz + ne;

    // --- CSR build (unordered row placement) ---
    k_zero<<<(SCAN_N + 255) / 256, 256>>>();
    k_count<<<(tot + 255) / 256, 256>>>(frow, erow, nnz, ne);
    {
        dim3 grid((NN + 1023) / 1024, 2);
        k_offsets<<<grid, 1024>>>();
    }
    k_fill<<<(tot + 255) / 256, 256>>>(frow, fcol, fval, erow, ecol, ew, nnz, ne);

    // --- forward pass (fused) ---
    k_feat_gather<<<(NN * 32 + 255) / 256, 256>>>(W1, b1);
    k_prop_dense<<<NN / 8, 256>>>(W2, b2);
    k_zq<<<NN / 8, 256>>>(out);
}